// round 8
// baseline (speedup 1.0000x reference)
#include <cuda_runtime.h>

// Adaptive threshold spike encoding — FINAL (measured machine floor).
// x: [B=32, F=65536] f32.  out: [B=32, T=32, F=65536] f32.
//
// Conclusion from 6 probed configs (STG / STG.cs / TMA bulk-store /
// persistent grid / 512-thread blocks): all converge at 41.8-44.2 us
// kernel, ~5.2 TB/s DRAM write. Model: every output byte transits LTS
// twice (L2 fill + dirty writeback), so total LTS traffic = 2*256MB+8MB
// = 520 MB / 42 us = ~12.4 TB/s = the path-independent LTS cap at NAT
// clock. All GMEM store paths (STG and TMA alike) transit L2 on sm_103a,
// and the output byte count is fixed by the problem -> ~42 us kernel is
// the hard floor. Best shape: 2048 blocks x 256 threads, one float4 per
// thread, 32 regs, exact-fit grid (no bounds check), coalesced STG.128
// evict-first stores.

#define TIMESTEPS 32
#define F_DIM 65536
#define F4_DIM (F_DIM / 4)      // 16384 float4 per feature row
#define RATE 0.1f
#define OMR 0.9f
#define THR0 0.5f
#define THREADS 256

__global__ __launch_bounds__(THREADS)
void adaptive_threshold_kernel(const float4* __restrict__ x,
                               float4* __restrict__ out) {
    int i = blockIdx.x * THREADS + threadIdx.x;   // float4 index (exact fit)

    float4 xv = __ldcs(&x[i]);

    // element index -> (batch, feature4)
    int e  = i << 2;                 // element index of lane 0 of this float4
    int b  = e >> 16;                // batch = e / 65536
    int f4 = (e & (F_DIM - 1)) >> 2; // float4 slot within the feature row

    float xx[4] = {xv.x, xv.y, xv.z, xv.w};
    float ad[4], acc[4], thr[4];
#pragma unroll
    for (int l = 0; l < 4; l++) {
        ad[l]  = RATE * fabsf(xx[l]);
        acc[l] = 0.0f;
        thr[l] = THR0;
    }

    // out[b][t][f]: base of this (b, f4) column, stride F4_DIM per timestep
    float4* ob = out + (size_t)b * (TIMESTEPS * F4_DIM) + f4;

#pragma unroll
    for (int t = 0; t < TIMESTEPS; t++) {
        float s[4];
#pragma unroll
        for (int l = 0; l < 4; l++) {
            acc[l] = acc[l] + xx[l];
            bool m = (acc[l] >= thr[l]);
            s[l]   = m ? 1.0f : 0.0f;
            acc[l] = m ? 0.0f : acc[l];
            thr[l] = thr[l] * OMR + ad[l];
        }
        float4 sv;
        sv.x = s[0]; sv.y = s[1]; sv.z = s[2]; sv.w = s[3];
        __stcs(ob + (size_t)t * F4_DIM, sv);
    }
}

extern "C" void kernel_launch(void* const* d_in, const int* in_sizes, int n_in,
                              void* d_out, int out_size) {
    const float4* x = (const float4*)d_in[0];
    float4* out = (float4*)d_out;
    int n4 = in_sizes[0] / 4;              // 524,288 — divisible by THREADS
    int blocks = n4 / THREADS;             // 2048
    adaptive_threshold_kernel<<<blocks, THREADS>>>(x, out);
}

// round 9
// speedup vs baseline: 1.2240x; 1.2240x over previous
#include <cuda_runtime.h>

// Adaptive threshold spike encoding — FINAL (measured machine floor).
// x: [B=32, F=65536] f32.  out: [B=32, T=32, F=65536] f32.
//
// Model, confirmed across 7 runs / 6 configs (STG / STG.cs / TMA bulk /
// persistent / 512-thr blocks): the binding resource is the LTS write path
// (SM-clock domain). Each output byte transits L2 twice (store fill +
// dirty writeback): 2*256MB + 8MB = 520 MB / 42 us = ~12.4 TB/s = the
// path-independent LTS cap at ~1.9 GHz NAT. Evidence: (a) STG, STG.cs and
// TMA bulk-store all tie at 41.8-42.3 us; (b) a DVFS-throttled run (R8)
// slowed exactly proportionally to SM clock with identical cycle count,
// which a DRAM-device-bound kernel would not.
// Output bytes are fixed by the problem -> ~80K cycles is the hard floor.
//
// Best shape: 2048 blocks x 256 threads, one float4 per thread, 32 regs,
// exact-fit grid, coalesced STG.128 evict-first stores.

#define TIMESTEPS 32
#define F_DIM 65536
#define F4_DIM (F_DIM / 4)      // 16384 float4 per feature row
#define RATE 0.1f
#define OMR 0.9f
#define THR0 0.5f
#define THREADS 256

__global__ __launch_bounds__(THREADS)
void adaptive_threshold_kernel(const float4* __restrict__ x,
                               float4* __restrict__ out) {
    int i = blockIdx.x * THREADS + threadIdx.x;   // float4 index (exact fit)

    float4 xv = __ldcs(&x[i]);

    // element index -> (batch, feature4)
    int e  = i << 2;                 // element index of lane 0 of this float4
    int b  = e >> 16;                // batch = e / 65536
    int f4 = (e & (F_DIM - 1)) >> 2; // float4 slot within the feature row

    float xx[4] = {xv.x, xv.y, xv.z, xv.w};
    float ad[4], acc[4], thr[4];
#pragma unroll
    for (int l = 0; l < 4; l++) {
        ad[l]  = RATE * fabsf(xx[l]);
        acc[l] = 0.0f;
        thr[l] = THR0;
    }

    // out[b][t][f]: base of this (b, f4) column, stride F4_DIM per timestep
    float4* ob = out + (size_t)b * (TIMESTEPS * F4_DIM) + f4;

#pragma unroll
    for (int t = 0; t < TIMESTEPS; t++) {
        float s[4];
#pragma unroll
        for (int l = 0; l < 4; l++) {
            acc[l] = acc[l] + xx[l];
            bool m = (acc[l] >= thr[l]);
            s[l]   = m ? 1.0f : 0.0f;
            acc[l] = m ? 0.0f : acc[l];
            thr[l] = thr[l] * OMR + ad[l];
        }
        float4 sv;
        sv.x = s[0]; sv.y = s[1]; sv.z = s[2]; sv.w = s[3];
        __stcs(ob + (size_t)t * F4_DIM, sv);
    }
}

extern "C" void kernel_launch(void* const* d_in, const int* in_sizes, int n_in,
                              void* d_out, int out_size) {
    const float4* x = (const float4*)d_in[0];
    float4* out = (float4*)d_out;
    int n4 = in_sizes[0] / 4;              // 524,288 — divisible by THREADS
    int blocks = n4 / THREADS;             // 2048
    adaptive_threshold_kernel<<<blocks, THREADS>>>(x, out);
}

// round 10
// speedup vs baseline: 1.2257x; 1.0014x over previous
#include <cuda_runtime.h>

// Adaptive threshold spike encoding — FINAL (measured machine floor).
// x: [B=32, F=65536] f32.  out: [B=32, T=32, F=65536] f32.
//
// Closed model, 9 rounds / 6 configs (STG / STG.cs / TMA bulk / persistent /
// 512-thr blocks / throttled replay):
//   - Fixed traffic: 256 MB write + 8 MB read (output bytes set by problem).
//   - Binding resource: LTS write path (SM-clock domain). Each output byte
//     transits L2 twice (store fill + dirty writeback): 520 MB / 42 us
//     ~= 12.4 TB/s ~= path-independent ~6300 B/cyc LTS cap at NAT clock.
//   - Evidence: STG == STG.cs == TMA bulk within 0.5 us (all store paths
//     transit L2 on sm_103a); a DVFS-throttled run slowed proportionally to
//     SM clock at identical cycle count (DRAM-device-bound would not);
//     occupancy 51-95% and issue 12-35% have no effect.
//   => ~80K cycles (~42 us kernel) is the hard floor for this op on GB300.
//
// Best shape: 2048 blocks x 256 threads, one float4 per thread, 32 regs,
// exact-fit grid (no bounds check), coalesced STG.128 evict-first stores,
// fully unrolled 32-timestep loop (pure FFMA/FSEL recurrence, no spills).

#define TIMESTEPS 32
#define F_DIM 65536
#define F4_DIM (F_DIM / 4)      // 16384 float4 per feature row
#define RATE 0.1f
#define OMR 0.9f
#define THR0 0.5f
#define THREADS 256

__global__ __launch_bounds__(THREADS)
void adaptive_threshold_kernel(const float4* __restrict__ x,
                               float4* __restrict__ out) {
    int i = blockIdx.x * THREADS + threadIdx.x;   // float4 index (exact fit)

    float4 xv = __ldcs(&x[i]);

    // element index -> (batch, feature4)
    int e  = i << 2;                 // element index of lane 0 of this float4
    int b  = e >> 16;                // batch = e / 65536
    int f4 = (e & (F_DIM - 1)) >> 2; // float4 slot within the feature row

    float xx[4] = {xv.x, xv.y, xv.z, xv.w};
    float ad[4], acc[4], thr[4];
#pragma unroll
    for (int l = 0; l < 4; l++) {
        ad[l]  = RATE * fabsf(xx[l]);
        acc[l] = 0.0f;
        thr[l] = THR0;
    }

    // out[b][t][f]: base of this (b, f4) column, stride F4_DIM per timestep
    float4* ob = out + (size_t)b * (TIMESTEPS * F4_DIM) + f4;

#pragma unroll
    for (int t = 0; t < TIMESTEPS; t++) {
        float s[4];
#pragma unroll
        for (int l = 0; l < 4; l++) {
            acc[l] = acc[l] + xx[l];
            bool m = (acc[l] >= thr[l]);
            s[l]   = m ? 1.0f : 0.0f;
            acc[l] = m ? 0.0f : acc[l];
            thr[l] = thr[l] * OMR + ad[l];
        }
        float4 sv;
        sv.x = s[0]; sv.y = s[1]; sv.z = s[2]; sv.w = s[3];
        __stcs(ob + (size_t)t * F4_DIM, sv);
    }
}

extern "C" void kernel_launch(void* const* d_in, const int* in_sizes, int n_in,
                              void* d_out, int out_size) {
    const float4* x = (const float4*)d_in[0];
    float4* out = (float4*)d_out;
    int n4 = in_sizes[0] / 4;              // 524,288 — divisible by THREADS
    int blocks = n4 / THREADS;             // 2048
    adaptive_threshold_kernel<<<blocks, THREADS>>>(x, out);
}